// round 1
// baseline (speedup 1.0000x reference)
#include <cuda_runtime.h>
#include <math.h>

#define NNODE 50000
#define NEDGE 500000
#define DMAX  256
#define EPS_SM 1e-16f
#define EPS_LN 1e-5f
#define NEG_SLOPE 0.2f

// ---------------- scratch (device globals; no allocation allowed) ----------------
__device__ float g_h[NNODE * DMAX];      // GEMM output (pre-aggregation features)
__device__ float g_feat[NNODE * DMAX];   // layer input features (post LN+ELU)
__device__ float g_agg[NNODE * DMAX];    // aggregated messages
__device__ float g_alpha[NEDGE * 4];     // edge attention (a_exp, then normalized)
__device__ float g_denom[NNODE * 4];     // softmax denominators
__device__ float g_ssrc[NNODE * 4];      // per-node source scores
__device__ float g_sdst[NNODE * 4];      // per-node dest scores
__device__ int   g_cnt[NNODE];
__device__ int   g_rptr[NNODE + 1];
__device__ int   g_fill[NNODE];
__device__ int   g_redges[NEDGE];

// ---------------- utility ----------------
__global__ void zero_i(int* p, int n) {
    int i = blockIdx.x * blockDim.x + threadIdx.x;
    if (i < n) p[i] = 0;
}
__global__ void zero_f(float* p, int n) {
    int i = blockIdx.x * blockDim.x + threadIdx.x;
    if (i < n) p[i] = 0.0f;
}

// ---------------- CSR build (group edges by row) ----------------
__global__ void hist_kernel(const int* __restrict__ row, int* cnt, int e) {
    int i = blockIdx.x * blockDim.x + threadIdx.x;
    if (i < e) atomicAdd(&cnt[row[i]], 1);
}

__global__ void scan_kernel(const int* __restrict__ cnt, int* ptr, int* fill, int n) {
    __shared__ int sh[1024];
    __shared__ int carry;
    if (threadIdx.x == 0) carry = 0;
    __syncthreads();
    for (int base = 0; base < n; base += 1024) {
        int i = base + threadIdx.x;
        int v = (i < n) ? cnt[i] : 0;
        sh[threadIdx.x] = v;
        __syncthreads();
        for (int off = 1; off < 1024; off <<= 1) {
            int t = (threadIdx.x >= off) ? sh[threadIdx.x - off] : 0;
            __syncthreads();
            sh[threadIdx.x] += t;
            __syncthreads();
        }
        int excl = sh[threadIdx.x] - v;
        if (i < n) { ptr[i] = carry + excl; fill[i] = carry + excl; }
        __syncthreads();
        if (threadIdx.x == 1023) carry += sh[1023];
        __syncthreads();
    }
    if (threadIdx.x == 0) ptr[n] = carry;
}

__global__ void scatter_kernel(const int* __restrict__ row, int* fill, int* redges, int e) {
    int i = blockIdx.x * blockDim.x + threadIdx.x;
    if (i < e) {
        int pos = atomicAdd(&fill[row[i]], 1);
        redges[pos] = i;
    }
}

// ---------------- SGEMM: C[M,Nn] = A[M,K] @ B[K,Nn] ----------------
// 64x64 tile, BK=16, 256 threads, 4x4 per thread, float4 loads.
#define BM 64
#define BN 64
#define BK 16
__global__ __launch_bounds__(256) void sgemm_kernel(
    const float* __restrict__ A, const float* __restrict__ B, float* __restrict__ C,
    int M, int K, int Nn)
{
    __shared__ float As[BK][BM];   // transposed: As[k][m]
    __shared__ float Bs[BK][BN];
    int tid = threadIdx.x;
    int tx = tid & 15, ty = tid >> 4;
    int m0 = blockIdx.y * BM, n0 = blockIdx.x * BN;

    int la = tid * 4;
    int ar = la >> 4, ac = la & 15;   // A tile element (row ar, col ac..ac+3)
    int lb = tid * 4;
    int br = lb >> 6, bc = lb & 63;   // B tile element (row br, col bc..bc+3)

    float acc[4][4];
#pragma unroll
    for (int i = 0; i < 4; i++)
#pragma unroll
        for (int j = 0; j < 4; j++) acc[i][j] = 0.0f;

    for (int k0 = 0; k0 < K; k0 += BK) {
        float4 av;
        if (m0 + ar < M)
            av = *reinterpret_cast<const float4*>(A + (size_t)(m0 + ar) * K + k0 + ac);
        else
            av = make_float4(0.f, 0.f, 0.f, 0.f);
        As[ac + 0][ar] = av.x;
        As[ac + 1][ar] = av.y;
        As[ac + 2][ar] = av.z;
        As[ac + 3][ar] = av.w;
        float4 bv = *reinterpret_cast<const float4*>(B + (size_t)(k0 + br) * Nn + n0 + bc);
        *reinterpret_cast<float4*>(&Bs[br][bc]) = bv;
        __syncthreads();
#pragma unroll
        for (int k = 0; k < BK; k++) {
            float4 a4 = *reinterpret_cast<const float4*>(&As[k][ty * 4]);
            float4 b4 = *reinterpret_cast<const float4*>(&Bs[k][tx * 4]);
            float a[4] = {a4.x, a4.y, a4.z, a4.w};
            float b[4] = {b4.x, b4.y, b4.z, b4.w};
#pragma unroll
            for (int i = 0; i < 4; i++)
#pragma unroll
                for (int j = 0; j < 4; j++) acc[i][j] += a[i] * b[j];
        }
        __syncthreads();
    }
#pragma unroll
    for (int i = 0; i < 4; i++) {
        int m = m0 + ty * 4 + i;
        if (m < M) {
            float4 v = make_float4(acc[i][0], acc[i][1], acc[i][2], acc[i][3]);
            *reinterpret_cast<float4*>(C + (size_t)m * Nn + n0 + tx * 4) = v;
        }
    }
}

// ---------------- per-node attention scores ----------------
// warp per (node, head): s = sum_c h[n,h,c] * a[h,c]
__global__ void attn_scores_kernel(
    const float* __restrict__ h, const float* __restrict__ asrc, const float* __restrict__ adst,
    float* __restrict__ ssrc, float* __restrict__ sdst, int n, int H, int C)
{
    int wid = (blockIdx.x * blockDim.x + threadIdx.x) >> 5;
    int lane = threadIdx.x & 31;
    if (wid >= n * H) return;
    int node = wid / H, hh = wid - node * H;
    const float* hp = h + (size_t)node * H * C + hh * C;
    const float* ap = asrc + hh * C;
    const float* dp = adst + hh * C;
    float ss = 0.f, sd = 0.f;
    for (int c = lane; c < C; c += 32) {
        float v = hp[c];
        ss += v * ap[c];
        sd += v * dp[c];
    }
#pragma unroll
    for (int o = 16; o; o >>= 1) {
        ss += __shfl_xor_sync(0xffffffffu, ss, o);
        sd += __shfl_xor_sync(0xffffffffu, sd, o);
    }
    if (lane == 0) { ssrc[wid] = ss; sdst[wid] = sd; }
}

// ---------------- edge scores: a_exp + denominator ----------------
__global__ void edge_scores_kernel(
    const int* __restrict__ row, const int* __restrict__ col, const float* __restrict__ ew,
    const float* __restrict__ ssrc, const float* __restrict__ sdst,
    float* __restrict__ aexp, float* __restrict__ denom, int e, int H)
{
    int i = blockIdx.x * blockDim.x + threadIdx.x;
    if (i >= e) return;
    int r = row[i], c = col[i];
    float w = ew[i];
    for (int h = 0; h < 4; h++) {
        if (h >= H) break;
        float v = ssrc[r * H + h] + sdst[c * H + h];
        v = (v >= 0.f) ? v : NEG_SLOPE * v;
        v = expf(v * w);
        aexp[i * H + h] = v;
        atomicAdd(&denom[c * H + h], v);
    }
}

// ---------------- normalize alpha ----------------
__global__ void normalize_kernel(
    const int* __restrict__ col, float* __restrict__ alpha, const float* __restrict__ denom,
    int e, int H)
{
    int i = blockIdx.x * blockDim.x + threadIdx.x;
    if (i >= e * H) return;
    int ed = i / H, h = i - ed * H;
    int c = col[ed];
    alpha[i] = alpha[i] / (denom[c * H + h] + EPS_SM);
}

// ---------------- aggregation: warp per node, gather over row-CSR ----------------
template <int NK, int CSHIFT>
__global__ __launch_bounds__(256) void aggregate_kernel(
    const float* __restrict__ h, const float* __restrict__ alpha, const int* __restrict__ col,
    const int* __restrict__ rptr, const int* __restrict__ redges,
    const float* __restrict__ bias, float* __restrict__ out, int n)
{
    const int H = (NK * 32) >> CSHIFT;
    const int D = NK * 32;
    int warp = (blockIdx.x * blockDim.x + threadIdx.x) >> 5;
    int lane = threadIdx.x & 31;
    if (warp >= n) return;
    float acc[NK];
#pragma unroll
    for (int k = 0; k < NK; k++) acc[k] = 0.f;
    int s = rptr[warp], epd = rptr[warp + 1];
    for (int i = s; i < epd; i++) {
        int e = redges[i];
        int c = col[e];
        const float* hp = h + (size_t)c * D;
        const float* ap = alpha + (size_t)e * H;
#pragma unroll
        for (int k = 0; k < NK; k++) {
            int d = k * 32 + lane;
            int hh = d >> CSHIFT;
            acc[k] += ap[hh] * hp[d];
        }
    }
#pragma unroll
    for (int k = 0; k < NK; k++) {
        int d = k * 32 + lane;
        out[(size_t)warp * D + d] = acc[k] + bias[d];
    }
}

// ---------------- layernorm (+ optional ELU), warp per node ----------------
template <int DK>
__global__ __launch_bounds__(256) void ln_kernel(
    const float* __restrict__ in, const float* __restrict__ g, const float* __restrict__ b,
    float* __restrict__ out, int n, int do_elu)
{
    const int D = DK * 32;
    int warp = (blockIdx.x * blockDim.x + threadIdx.x) >> 5;
    int lane = threadIdx.x & 31;
    if (warp >= n) return;
    float v[DK];
    float sum = 0.f, sumsq = 0.f;
#pragma unroll
    for (int k = 0; k < DK; k++) {
        v[k] = in[(size_t)warp * D + k * 32 + lane];
        sum += v[k];
        sumsq += v[k] * v[k];
    }
#pragma unroll
    for (int o = 16; o; o >>= 1) {
        sum += __shfl_xor_sync(0xffffffffu, sum, o);
        sumsq += __shfl_xor_sync(0xffffffffu, sumsq, o);
    }
    float mu = sum / (float)D;
    float var = sumsq / (float)D - mu * mu;
    float r = rsqrtf(var + EPS_LN);
#pragma unroll
    for (int k = 0; k < DK; k++) {
        int d = k * 32 + lane;
        float y = (v[k] - mu) * r * g[d] + b[d];
        if (do_elu) y = (y > 0.f) ? y : expm1f(y);
        out[(size_t)warp * D + d] = y;
    }
}

// ---------------- host orchestration ----------------
static inline int ceil_div(int a, int b) { return (a + b - 1) / b; }

extern "C" void kernel_launch(void* const* d_in, const int* in_sizes, int n_in,
                              void* d_out, int out_size) {
    const float* x   = (const float*)d_in[0];
    const int*   ei  = (const int*)d_in[1];
    const float* ew  = (const float*)d_in[2];
    const float* W1  = (const float*)d_in[3];
    const float* as1 = (const float*)d_in[4];
    const float* ad1 = (const float*)d_in[5];
    const float* b1  = (const float*)d_in[6];
    const float* g1  = (const float*)d_in[7];
    const float* be1 = (const float*)d_in[8];
    const float* W2  = (const float*)d_in[9];
    const float* as2 = (const float*)d_in[10];
    const float* ad2 = (const float*)d_in[11];
    const float* b2  = (const float*)d_in[12];
    const float* g2  = (const float*)d_in[13];
    const float* be2 = (const float*)d_in[14];
    const float* W3  = (const float*)d_in[15];
    const float* as3 = (const float*)d_in[16];
    const float* ad3 = (const float*)d_in[17];
    const float* b3  = (const float*)d_in[18];
    const float* g3  = (const float*)d_in[19];
    const float* be3 = (const float*)d_in[20];
    float* out = (float*)d_out;

    const int* row = ei;
    const int* col = ei + NEDGE;

    float *h, *feat, *agg, *alpha, *denom, *ssrc, *sdst;
    int *cnt, *rptr, *fill, *redges;
    cudaGetSymbolAddress((void**)&h, g_h);
    cudaGetSymbolAddress((void**)&feat, g_feat);
    cudaGetSymbolAddress((void**)&agg, g_agg);
    cudaGetSymbolAddress((void**)&alpha, g_alpha);
    cudaGetSymbolAddress((void**)&denom, g_denom);
    cudaGetSymbolAddress((void**)&ssrc, g_ssrc);
    cudaGetSymbolAddress((void**)&sdst, g_sdst);
    cudaGetSymbolAddress((void**)&cnt, g_cnt);
    cudaGetSymbolAddress((void**)&rptr, g_rptr);
    cudaGetSymbolAddress((void**)&fill, g_fill);
    cudaGetSymbolAddress((void**)&redges, g_redges);

    const int TB = 256;
    const int eb = ceil_div(NEDGE, TB);

    // ---- CSR build (by row) ----
    zero_i<<<ceil_div(NNODE, TB), TB>>>(cnt, NNODE);
    hist_kernel<<<eb, TB>>>(row, cnt, NEDGE);
    scan_kernel<<<1, 1024>>>(cnt, rptr, fill, NNODE);
    scatter_kernel<<<eb, TB>>>(row, fill, redges, NEDGE);

    // =============== Layer 1: in=x[384] -> D=256, H=4, C=64 ===============
    {
        dim3 grid(256 / BN, ceil_div(NNODE, BM));
        sgemm_kernel<<<grid, 256>>>(x, W1, h, NNODE, 384, 256);
        int swarps = NNODE * 4;
        attn_scores_kernel<<<ceil_div(swarps * 32, TB), TB>>>(h, as1, ad1, ssrc, sdst, NNODE, 4, 64);
        zero_f<<<ceil_div(NNODE * 4, TB), TB>>>(denom, NNODE * 4);
        edge_scores_kernel<<<eb, TB>>>(row, col, ew, ssrc, sdst, alpha, denom, NEDGE, 4);
        normalize_kernel<<<ceil_div(NEDGE * 4, TB), TB>>>(col, alpha, denom, NEDGE, 4);
        aggregate_kernel<8, 6><<<ceil_div(NNODE * 32, TB), TB>>>(h, alpha, col, rptr, redges, b1, agg, NNODE);
        ln_kernel<8><<<ceil_div(NNODE * 32, TB), TB>>>(agg, g1, be1, feat, NNODE, 1);
    }

    // =============== Layer 2: in=feat[256] -> D=256, H=4, C=64 ===============
    {
        dim3 grid(256 / BN, ceil_div(NNODE, BM));
        sgemm_kernel<<<grid, 256>>>(feat, W2, h, NNODE, 256, 256);
        int swarps = NNODE * 4;
        attn_scores_kernel<<<ceil_div(swarps * 32, TB), TB>>>(h, as2, ad2, ssrc, sdst, NNODE, 4, 64);
        zero_f<<<ceil_div(NNODE * 4, TB), TB>>>(denom, NNODE * 4);
        edge_scores_kernel<<<eb, TB>>>(row, col, ew, ssrc, sdst, alpha, denom, NEDGE, 4);
        normalize_kernel<<<ceil_div(NEDGE * 4, TB), TB>>>(col, alpha, denom, NEDGE, 4);
        aggregate_kernel<8, 6><<<ceil_div(NNODE * 32, TB), TB>>>(h, alpha, col, rptr, redges, b2, agg, NNODE);
        ln_kernel<8><<<ceil_div(NNODE * 32, TB), TB>>>(agg, g2, be2, feat, NNODE, 1);
    }

    // =============== Layer 3: in=feat[256] -> D=128, H=1, C=128 ===============
    {
        dim3 grid(128 / BN, ceil_div(NNODE, BM));
        sgemm_kernel<<<grid, 256>>>(feat, W3, h, NNODE, 256, 128);
        int swarps = NNODE * 1;
        attn_scores_kernel<<<ceil_div(swarps * 32, TB), TB>>>(h, as3, ad3, ssrc, sdst, NNODE, 1, 128);
        zero_f<<<ceil_div(NNODE, TB), TB>>>(denom, NNODE);
        edge_scores_kernel<<<eb, TB>>>(row, col, ew, ssrc, sdst, alpha, denom, NEDGE, 1);
        normalize_kernel<<<ceil_div(NEDGE, TB), TB>>>(col, alpha, denom, NEDGE, 1);
        aggregate_kernel<4, 7><<<ceil_div(NNODE * 32, TB), TB>>>(h, alpha, col, rptr, redges, b3, agg, NNODE);
        ln_kernel<4><<<ceil_div(NNODE * 32, TB), TB>>>(agg, g3, be3, out, NNODE, 0);
    }
}

// round 3
// speedup vs baseline: 1.4197x; 1.4197x over previous
#include <cuda_runtime.h>
#include <cuda_bf16.h>
#include <math.h>
#include <stdint.h>

#define NNODE 50000
#define NEDGE 500000
#define DMAX  256
#define EPS_SM 1e-16f
#define EPS_LN 1e-5f
#define NEG_SLOPE 0.2f

// ---------------- scratch (device globals; no allocation allowed) ----------------
__device__ float g_h[NNODE * DMAX];              // GEMM output
__device__ float g_agg[NNODE * DMAX];            // aggregated messages
__device__ float g_alpha[NEDGE * 4];             // edge exp scores
__device__ float g_denom[NNODE * 4];             // denominators -> reciprocals
__device__ float g_ssrc[NNODE * 4];
__device__ float g_sdst[NNODE * 4];
__device__ int   g_cnt[NNODE];
__device__ int   g_rptr[NNODE + 1];
__device__ int   g_fill[NNODE];
__device__ int   g_redges[NEDGE];
__device__ __nv_bfloat16 g_ahi[NNODE * 384];     // activation hi (bf16), max K=384
__device__ __nv_bfloat16 g_alo[NNODE * 384];     // activation lo
__device__ __nv_bfloat16 g_wthi[256 * 384];      // transposed weight hi [N][K]
__device__ __nv_bfloat16 g_wtlo[256 * 384];      // transposed weight lo

// ================= PTX helpers =================
__device__ __forceinline__ uint32_t smem_u32(const void* p) {
    uint32_t a;
    asm("{ .reg .u64 t; cvta.to.shared.u64 t, %1; cvt.u32.u64 %0, t; }" : "=r"(a) : "l"(p));
    return a;
}

#define CPA16(dst, src, sz) \
    asm volatile("cp.async.cg.shared.global [%0], [%1], 16, %2;" \
                 :: "r"(dst), "l"(src), "r"(sz))
#define CPA_COMMIT() asm volatile("cp.async.commit_group;" ::: "memory")
#define CPA_WAIT(n)  asm volatile("cp.async.wait_group %0;" :: "n"(n) : "memory")

#define LDMX4(r0, r1, r2, r3, addr) \
    asm volatile("ldmatrix.sync.aligned.m8n8.x4.shared.b16 {%0,%1,%2,%3}, [%4];" \
                 : "=r"(r0), "=r"(r1), "=r"(r2), "=r"(r3) : "r"(addr))

__device__ __forceinline__ void mma16816(float* c, const uint32_t* a, const uint32_t* b) {
    asm volatile(
        "mma.sync.aligned.m16n8k16.row.col.f32.bf16.bf16.f32 "
        "{%0,%1,%2,%3}, {%4,%5,%6,%7}, {%8,%9}, {%0,%1,%2,%3};"
        : "+f"(c[0]), "+f"(c[1]), "+f"(c[2]), "+f"(c[3])
        : "r"(a[0]), "r"(a[1]), "r"(a[2]), "r"(a[3]), "r"(b[0]), "r"(b[1]));
}

// swizzle for 64B rows: permute 16B units by row bits (conflict-free ldmatrix)
#define SWZ64(b) ((b) ^ (((b) >> 3) & 0x30))

// ---------------- utility ----------------
__global__ void zero_i(int* p, int n) {
    int i = blockIdx.x * blockDim.x + threadIdx.x;
    if (i < n) p[i] = 0;
}
__global__ void zero_f(float* p, int n) {
    int i = blockIdx.x * blockDim.x + threadIdx.x;
    if (i < n) p[i] = 0.0f;
}

// ---------------- weight prep: transpose + bf16 split ----------------
__global__ void wprep_kernel(const float* __restrict__ W, __nv_bfloat16* hi,
                             __nv_bfloat16* lo, int K, int Nn) {
    int i = blockIdx.x * blockDim.x + threadIdx.x;
    if (i >= K * Nn) return;
    int n = i / K, k = i - n * K;
    float v = W[(size_t)k * Nn + n];
    __nv_bfloat16 h = __float2bfloat16(v);
    hi[i] = h;
    lo[i] = __float2bfloat16(v - __bfloat162float(h));
}

// ---------------- activation split (layer-1 input x) ----------------
__global__ void asplit_kernel(const float* __restrict__ A, __nv_bfloat16* hi,
                              __nv_bfloat16* lo, int total) {
    int i = blockIdx.x * blockDim.x + threadIdx.x;
    if (i >= total) return;
    float v = A[i];
    __nv_bfloat16 h = __float2bfloat16(v);
    hi[i] = h;
    lo[i] = __float2bfloat16(v - __bfloat162float(h));
}

// ---------------- CSR build ----------------
__global__ void hist_kernel(const int* __restrict__ row, int* cnt, int e) {
    int i = blockIdx.x * blockDim.x + threadIdx.x;
    if (i < e) atomicAdd(&cnt[row[i]], 1);
}

__global__ void scan_kernel(const int* __restrict__ cnt, int* ptr, int* fill, int n) {
    __shared__ int sh[1024];
    __shared__ int carry;
    if (threadIdx.x == 0) carry = 0;
    __syncthreads();
    for (int base = 0; base < n; base += 1024) {
        int i = base + threadIdx.x;
        int v = (i < n) ? cnt[i] : 0;
        sh[threadIdx.x] = v;
        __syncthreads();
        for (int off = 1; off < 1024; off <<= 1) {
            int t = (threadIdx.x >= off) ? sh[threadIdx.x - off] : 0;
            __syncthreads();
            sh[threadIdx.x] += t;
            __syncthreads();
        }
        int excl = sh[threadIdx.x] - v;
        if (i < n) { ptr[i] = carry + excl; fill[i] = carry + excl; }
        __syncthreads();
        if (threadIdx.x == 1023) carry += sh[1023];
        __syncthreads();
    }
    if (threadIdx.x == 0) ptr[n] = carry;
}

__global__ void scatter_kernel(const int* __restrict__ row, int* fill, int* redges, int e) {
    int i = blockIdx.x * blockDim.x + threadIdx.x;
    if (i < e) {
        int pos = atomicAdd(&fill[row[i]], 1);
        redges[pos] = i;
    }
}

// ============ HMMA split-bf16 GEMM: C[M,NN] = A[M,KK] @ Wt^T ============
// A given as hi/lo bf16 [M][KK]; Wt hi/lo bf16 [NN][KK].
// CTA tile 128(m) x 64(n), BK=32, 8 warps (4m x 2n), warp tile 32x32.
// grid: (NN/64, mtiles)  — n-tile fastest for A reuse in L2.
template <int NN, int KK>
__global__ __launch_bounds__(256) void gemm_mma(
    const __nv_bfloat16* __restrict__ Ahi, const __nv_bfloat16* __restrict__ Alo,
    const __nv_bfloat16* __restrict__ Bhi, const __nv_bfloat16* __restrict__ Blo,
    float* __restrict__ C, int M)
{
    constexpr int BK = 32;
    constexpr int NCH = KK / BK;
    constexpr int STG = 24576;   // A hi 8K + A lo 8K + B hi 4K + B lo 4K
    extern __shared__ char smem[];
    uint32_t sb = smem_u32(smem);

    int tid = threadIdx.x;
    int lane = tid & 31, wid = tid >> 5;
    int wm = wid & 3, wn = wid >> 2;
    int m0 = blockIdx.y * 128;
    int n0 = blockIdx.x * 64;

    // ---- precompute ldmatrix addresses (stage-relative) ----
    int g = lane >> 3, lr = lane & 7;
    uint32_t aoff[2][2], boff[2][2];
#pragma unroll
    for (int mt = 0; mt < 2; mt++)
#pragma unroll
        for (int ks = 0; ks < 2; ks++) {
            int row = wm * 32 + mt * 16 + (g & 1) * 8 + lr;
            int unit = ks * 2 + (g >> 1);
            int b = row * 64 + unit * 16;
            aoff[mt][ks] = SWZ64(b);
        }
#pragma unroll
    for (int np = 0; np < 2; np++)
#pragma unroll
        for (int ks = 0; ks < 2; ks++) {
            int row = wn * 32 + np * 16 + (g >> 1) * 8 + lr;
            int unit = ks * 2 + (g & 1);
            int b = row * 64 + unit * 16;
            boff[np][ks] = 16384u + SWZ64(b);
        }

    // ---- per-thread cp.async slots ----
    // A: chunks tid and tid+256 of 512 (128 rows x 4 units), both splits.
    // B: chunk tid of 256 (64 rows x 4 units), both splits.
    int ar0 = tid >> 2, au0 = tid & 3;
    int ar1 = (tid + 256) >> 2, au1 = tid & 3;
    uint32_t asw0 = SWZ64(ar0 * 64 + au0 * 16);
    uint32_t asw1 = SWZ64(ar1 * 64 + au1 * 16);
    int br = tid >> 2, bu = tid & 3;
    uint32_t bsw = SWZ64(br * 64 + bu * 16);
    long bofs = (long)(n0 + br) * KK + bu * 8;

    float acc[2][4][4];
#pragma unroll
    for (int mt = 0; mt < 2; mt++)
#pragma unroll
        for (int nt = 0; nt < 4; nt++)
#pragma unroll
            for (int j = 0; j < 4; j++) acc[mt][nt][j] = 0.f;

    auto load_stage = [&](int ch, uint32_t so) {
        int k0 = ch * BK;
        {
            int grow = m0 + ar0;
            int sz = (grow < M) ? 16 : 0;
            long go = (long)((grow < M) ? grow : 0) * KK + k0 + au0 * 8;
            CPA16(sb + so + asw0, Ahi + go, sz);
            CPA16(sb + so + 8192 + asw0, Alo + go, sz);
        }
        {
            int grow = m0 + ar1;
            int sz = (grow < M) ? 16 : 0;
            long go = (long)((grow < M) ? grow : 0) * KK + k0 + au1 * 8;
            CPA16(sb + so + asw1, Ahi + go, sz);
            CPA16(sb + so + 8192 + asw1, Alo + go, sz);
        }
        {
            long go = bofs + k0;
            CPA16(sb + so + 16384 + bsw, Bhi + go, 16);
            CPA16(sb + so + 20480 + bsw, Blo + go, 16);
        }
    };

    auto compute_stage = [&](uint32_t so) {
#pragma unroll
        for (int ks = 0; ks < 2; ks++) {
            uint32_t ah[2][4], al[2][4], bh[4][2], bl[4][2];
#pragma unroll
            for (int mt = 0; mt < 2; mt++) {
                LDMX4(ah[mt][0], ah[mt][1], ah[mt][2], ah[mt][3], sb + so + aoff[mt][ks]);
                LDMX4(al[mt][0], al[mt][1], al[mt][2], al[mt][3], sb + so + 8192 + aoff[mt][ks]);
            }
#pragma unroll
            for (int np = 0; np < 2; np++) {
                LDMX4(bh[2 * np][0], bh[2 * np][1], bh[2 * np + 1][0], bh[2 * np + 1][1],
                      sb + so + boff[np][ks]);
                LDMX4(bl[2 * np][0], bl[2 * np][1], bl[2 * np + 1][0], bl[2 * np + 1][1],
                      sb + so + 4096 + boff[np][ks]);
            }
#pragma unroll
            for (int mt = 0; mt < 2; mt++)
#pragma unroll
                for (int nt = 0; nt < 4; nt++) {
                    mma16816(acc[mt][nt], ah[mt], bh[nt]);
                    mma16816(acc[mt][nt], ah[mt], bl[nt]);
                    mma16816(acc[mt][nt], al[mt], bh[nt]);
                }
        }
    };

    load_stage(0, 0);
    CPA_COMMIT();
    uint32_t so = 0;
    for (int ch = 0; ch < NCH; ch++) {
        if (ch + 1 < NCH) {
            load_stage(ch + 1, so ^ STG);
            CPA_COMMIT();
            CPA_WAIT(1);
        } else {
            CPA_WAIT(0);
        }
        __syncthreads();
        compute_stage(so);
        __syncthreads();
        so ^= STG;
    }

    // ---- epilogue ----
#pragma unroll
    for (int mt = 0; mt < 2; mt++) {
        int m = m0 + wm * 32 + mt * 16 + (lane >> 2);
#pragma unroll
        for (int nt = 0; nt < 4; nt++) {
            int n = n0 + wn * 32 + nt * 8 + (lane & 3) * 2;
            if (m < M)
                *reinterpret_cast<float2*>(C + (size_t)m * NN + n) =
                    make_float2(acc[mt][nt][0], acc[mt][nt][1]);
            if (m + 8 < M)
                *reinterpret_cast<float2*>(C + (size_t)(m + 8) * NN + n) =
                    make_float2(acc[mt][nt][2], acc[mt][nt][3]);
        }
    }
}

// ---------------- per-node attention scores ----------------
__global__ void attn_scores_kernel(
    const float* __restrict__ h, const float* __restrict__ asrc, const float* __restrict__ adst,
    float* __restrict__ ssrc, float* __restrict__ sdst, int n, int H, int C)
{
    int wid = (blockIdx.x * blockDim.x + threadIdx.x) >> 5;
    int lane = threadIdx.x & 31;
    if (wid >= n * H) return;
    int node = wid / H, hh = wid - node * H;
    const float* hp = h + (size_t)node * H * C + hh * C;
    const float* ap = asrc + hh * C;
    const float* dp = adst + hh * C;
    float ss = 0.f, sd = 0.f;
    for (int c = lane; c < C; c += 32) {
        float v = hp[c];
        ss += v * ap[c];
        sd += v * dp[c];
    }
#pragma unroll
    for (int o = 16; o; o >>= 1) {
        ss += __shfl_xor_sync(0xffffffffu, ss, o);
        sd += __shfl_xor_sync(0xffffffffu, sd, o);
    }
    if (lane == 0) { ssrc[wid] = ss; sdst[wid] = sd; }
}

// ---------------- edge scores: a_exp + denominator ----------------
__global__ void edge_scores_kernel(
    const int* __restrict__ row, const int* __restrict__ col, const float* __restrict__ ew,
    const float* __restrict__ ssrc, const float* __restrict__ sdst,
    float* __restrict__ aexp, float* __restrict__ denom, int e, int H)
{
    int i = blockIdx.x * blockDim.x + threadIdx.x;
    if (i >= e) return;
    int r = row[i], c = col[i];
    float w = ew[i];
    for (int h = 0; h < 4; h++) {
        if (h >= H) break;
        float v = ssrc[r * H + h] + sdst[c * H + h];
        v = (v >= 0.f) ? v : NEG_SLOPE * v;
        v = expf(v * w);
        aexp[(size_t)i * H + h] = v;
        atomicAdd(&denom[c * H + h], v);
    }
}

// ---------------- reciprocal of denominators ----------------
__global__ void rdenom_kernel(float* d, int n) {
    int i = blockIdx.x * blockDim.x + threadIdx.x;
    if (i < n) d[i] = 1.0f / (d[i] + EPS_SM);
}

// ---------------- aggregation: warp per node over row-CSR ----------------
template <int NK, int CSHIFT>
__global__ __launch_bounds__(256) void aggregate_kernel(
    const float* __restrict__ h, const float* __restrict__ aexp, const float* __restrict__ rden,
    const int* __restrict__ col, const int* __restrict__ rptr, const int* __restrict__ redges,
    const float* __restrict__ bias, float* __restrict__ out, int n)
{
    constexpr int H = (NK * 32) >> CSHIFT;
    constexpr int D = NK * 32;
    int warp = (blockIdx.x * blockDim.x + threadIdx.x) >> 5;
    int lane = threadIdx.x & 31;
    if (warp >= n) return;
    float acc[NK];
#pragma unroll
    for (int k = 0; k < NK; k++) acc[k] = 0.f;
    int s = rptr[warp], eend = rptr[warp + 1];
    for (int i = s; i < eend; i++) {
        int e = redges[i];
        int c = col[e];
        float w[H];
        if constexpr (H == 4) {
            float4 a4 = *reinterpret_cast<const float4*>(aexp + (size_t)e * 4);
            float4 d4 = *reinterpret_cast<const float4*>(rden + (size_t)c * 4);
            w[0] = a4.x * d4.x; w[1] = a4.y * d4.y; w[2] = a4.z * d4.z; w[3] = a4.w * d4.w;
        } else {
            w[0] = aexp[e] * rden[c];
        }
        const float* hp = h + (size_t)c * D;
#pragma unroll
        for (int k = 0; k < NK; k++) acc[k] += w[(k * 32) >> CSHIFT] * hp[k * 32 + lane];
    }
#pragma unroll
    for (int k = 0; k < NK; k++) {
        int d = k * 32 + lane;
        out[(size_t)warp * D + d] = acc[k] + bias[d];
    }
}

// ---------------- LN+ELU -> bf16 hi/lo split (for next GEMM) ----------------
template <int DK>
__global__ __launch_bounds__(256) void ln_split_kernel(
    const float* __restrict__ in, const float* __restrict__ g, const float* __restrict__ b,
    __nv_bfloat16* __restrict__ hi, __nv_bfloat16* __restrict__ lo, int n)
{
    const int D = DK * 32;
    int warp = (blockIdx.x * blockDim.x + threadIdx.x) >> 5;
    int lane = threadIdx.x & 31;
    if (warp >= n) return;
    float v[DK];
    float sum = 0.f, sumsq = 0.f;
#pragma unroll
    for (int k = 0; k < DK; k++) {
        v[k] = in[(size_t)warp * D + k * 32 + lane];
        sum += v[k];
        sumsq += v[k] * v[k];
    }
#pragma unroll
    for (int o = 16; o; o >>= 1) {
        sum += __shfl_xor_sync(0xffffffffu, sum, o);
        sumsq += __shfl_xor_sync(0xffffffffu, sumsq, o);
    }
    float mu = sum / (float)D;
    float var = sumsq / (float)D - mu * mu;
    float r = rsqrtf(var + EPS_LN);
#pragma unroll
    for (int k = 0; k < DK; k++) {
        int d = k * 32 + lane;
        float y = (v[k] - mu) * r * g[d] + b[d];
        y = (y > 0.f) ? y : expm1f(y);
        __nv_bfloat16 hh = __float2bfloat16(y);
        hi[(size_t)warp * D + d] = hh;
        lo[(size_t)warp * D + d] = __float2bfloat16(y - __bfloat162float(hh));
    }
}

// ---------------- final layernorm (fp32 out) ----------------
template <int DK>
__global__ __launch_bounds__(256) void ln_kernel(
    const float* __restrict__ in, const float* __restrict__ g, const float* __restrict__ b,
    float* __restrict__ out, int n)
{
    const int D = DK * 32;
    int warp = (blockIdx.x * blockDim.x + threadIdx.x) >> 5;
    int lane = threadIdx.x & 31;
    if (warp >= n) return;
    float v[DK];
    float sum = 0.f, sumsq = 0.f;
#pragma unroll
    for (int k = 0; k < DK; k++) {
        v[k] = in[(size_t)warp * D + k * 32 + lane];
        sum += v[k];
        sumsq += v[k] * v[k];
    }
#pragma unroll
    for (int o = 16; o; o >>= 1) {
        sum += __shfl_xor_sync(0xffffffffu, sum, o);
        sumsq += __shfl_xor_sync(0xffffffffu, sumsq, o);
    }
    float mu = sum / (float)D;
    float var = sumsq / (float)D - mu * mu;
    float r = rsqrtf(var + EPS_LN);
#pragma unroll
    for (int k = 0; k < DK; k++) {
        int d = k * 32 + lane;
        out[(size_t)warp * D + d] = (v[k] - mu) * r * g[d] + b[d];
    }
}

// ---------------- host orchestration ----------------
static inline int ceil_div(int a, int b) { return (a + b - 1) / b; }

extern "C" void kernel_launch(void* const* d_in, const int* in_sizes, int n_in,
                              void* d_out, int out_size) {
    const float* x   = (const float*)d_in[0];
    const int*   ei  = (const int*)d_in[1];
    const float* ew  = (const float*)d_in[2];
    const float* W1  = (const float*)d_in[3];
    const float* as1 = (const float*)d_in[4];
    const float* ad1 = (const float*)d_in[5];
    const float* b1  = (const float*)d_in[6];
    const float* g1  = (const float*)d_in[7];
    const float* be1 = (const float*)d_in[8];
    const float* W2  = (const float*)d_in[9];
    const float* as2 = (const float*)d_in[10];
    const float* ad2 = (const float*)d_in[11];
    const float* b2  = (const float*)d_in[12];
    const float* g2  = (const float*)d_in[13];
    const float* be2 = (const float*)d_in[14];
    const float* W3  = (const float*)d_in[15];
    const float* as3 = (const float*)d_in[16];
    const float* ad3 = (const float*)d_in[17];
    const float* b3  = (const float*)d_in[18];
    const float* g3  = (const float*)d_in[19];
    const float* be3 = (const float*)d_in[20];
    float* out = (float*)d_out;

    const int* row = ei;
    const int* col = ei + NEDGE;

    float *h, *agg, *alpha, *denom, *ssrc, *sdst;
    int *cnt, *rptr, *fill, *redges;
    __nv_bfloat16 *ahi, *alo, *wthi, *wtlo;
    cudaGetSymbolAddress((void**)&h, g_h);
    cudaGetSymbolAddress((void**)&agg, g_agg);
    cudaGetSymbolAddress((void**)&alpha, g_alpha);
    cudaGetSymbolAddress((void**)&denom, g_denom);
    cudaGetSymbolAddress((void**)&ssrc, g_ssrc);
    cudaGetSymbolAddress((void**)&sdst, g_sdst);
    cudaGetSymbolAddress((void**)&cnt, g_cnt);
    cudaGetSymbolAddress((void**)&rptr, g_rptr);
    cudaGetSymbolAddress((void**)&fill, g_fill);
    cudaGetSymbolAddress((void**)&redges, g_redges);
    cudaGetSymbolAddress((void**)&ahi, g_ahi);
    cudaGetSymbolAddress((void**)&alo, g_alo);
    cudaGetSymbolAddress((void**)&wthi, g_wthi);
    cudaGetSymbolAddress((void**)&wtlo, g_wtlo);

    const int TB = 256;
    const int eb = ceil_div(NEDGE, TB);
    const int mtiles = ceil_div(NNODE, 128);
    const int SMEM = 49152;

    cudaFuncSetAttribute(gemm_mma<256, 384>, cudaFuncAttributeMaxDynamicSharedMemorySize, SMEM);
    cudaFuncSetAttribute(gemm_mma<256, 256>, cudaFuncAttributeMaxDynamicSharedMemorySize, SMEM);
    cudaFuncSetAttribute(gemm_mma<128, 256>, cudaFuncAttributeMaxDynamicSharedMemorySize, SMEM);

    // ---- CSR build (by row) ----
    zero_i<<<ceil_div(NNODE, TB), TB>>>(cnt, NNODE);
    hist_kernel<<<eb, TB>>>(row, cnt, NEDGE);
    scan_kernel<<<1, 1024>>>(cnt, rptr, fill, NNODE);
    scatter_kernel<<<eb, TB>>>(row, fill, redges, NEDGE);

    // =============== Layer 1: x[384] -> 256, H=4, C=64 ===============
    {
        asplit_kernel<<<ceil_div(NNODE * 384, TB), TB>>>(x, ahi, alo, NNODE * 384);
        wprep_kernel<<<ceil_div(384 * 256, TB), TB>>>(W1, wthi, wtlo, 384, 256);
        gemm_mma<256, 384><<<dim3(4, mtiles), 256, SMEM>>>(ahi, alo, wthi, wtlo, h, NNODE);
        attn_scores_kernel<<<ceil_div(NNODE * 4 * 32, TB), TB>>>(h, as1, ad1, ssrc, sdst, NNODE, 4, 64);
        zero_f<<<ceil_div(NNODE * 4, TB), TB>>>(denom, NNODE * 4);
        edge_scores_kernel<<<eb, TB>>>(row, col, ew, ssrc, sdst, alpha, denom, NEDGE, 4);
        rdenom_kernel<<<ceil_div(NNODE * 4, TB), TB>>>(denom, NNODE * 4);
        aggregate_kernel<8, 6><<<ceil_div(NNODE * 32, TB), TB>>>(h, alpha, denom, col, rptr, redges, b1, agg, NNODE);
        ln_split_kernel<8><<<ceil_div(NNODE * 32, TB), TB>>>(agg, g1, be1, ahi, alo, NNODE);
    }

    // =============== Layer 2: feat[256] -> 256, H=4, C=64 ===============
    {
        wprep_kernel<<<ceil_div(256 * 256, TB), TB>>>(W2, wthi, wtlo, 256, 256);
        gemm_mma<256, 256><<<dim3(4, mtiles), 256, SMEM>>>(ahi, alo, wthi, wtlo, h, NNODE);
        attn_scores_kernel<<<ceil_div(NNODE * 4 * 32, TB), TB>>>(h, as2, ad2, ssrc, sdst, NNODE, 4, 64);
        zero_f<<<ceil_div(NNODE * 4, TB), TB>>>(denom, NNODE * 4);
        edge_scores_kernel<<<eb, TB>>>(row, col, ew, ssrc, sdst, alpha, denom, NEDGE, 4);
        rdenom_kernel<<<ceil_div(NNODE * 4, TB), TB>>>(denom, NNODE * 4);
        aggregate_kernel<8, 6><<<ceil_div(NNODE * 32, TB), TB>>>(h, alpha, denom, col, rptr, redges, b2, agg, NNODE);
        ln_split_kernel<8><<<ceil_div(NNODE * 32, TB), TB>>>(agg, g2, be2, ahi, alo, NNODE);
    }

    // =============== Layer 3: feat[256] -> 128, H=1, C=128 ===============
    {
        wprep_kernel<<<ceil_div(256 * 128, TB), TB>>>(W3, wthi, wtlo, 256, 128);
        gemm_mma<128, 256><<<dim3(2, mtiles), 256, SMEM>>>(ahi, alo, wthi, wtlo, h, NNODE);
        attn_scores_kernel<<<ceil_div(NNODE * 32, TB), TB>>>(h, as3, ad3, ssrc, sdst, NNODE, 1, 128);
        zero_f<<<ceil_div(NNODE, TB), TB>>>(denom, NNODE);
        edge_scores_kernel<<<eb, TB>>>(row, col, ew, ssrc, sdst, alpha, denom, NEDGE, 1);
        rdenom_kernel<<<ceil_div(NNODE, TB), TB>>>(denom, NNODE);
        aggregate_kernel<4, 7><<<ceil_div(NNODE * 32, TB), TB>>>(h, alpha, denom, col, rptr, redges, b3, agg, NNODE);
        ln_kernel<4><<<ceil_div(NNODE * 32, TB), TB>>>(agg, g3, be3, out, NNODE);
    }
}

// round 4
// speedup vs baseline: 1.5689x; 1.1051x over previous
#include <cuda_runtime.h>
#include <cuda_bf16.h>
#include <math.h>
#include <stdint.h>

#define NNODE 50000
#define NEDGE 500000
#define DMAX  256
#define EPS_SM 1e-16f
#define EPS_LN 1e-5f
#define NEG_SLOPE 0.2f

// ---------------- scratch (device globals) ----------------
__device__ float g_h[NNODE * DMAX];
__device__ float g_agg[NNODE * DMAX];
__device__ float g_alpha[NEDGE * 4];
__device__ float g_denom[NNODE * 4];
__device__ float g_ssrc[NNODE * 4];
__device__ float g_sdst[NNODE * 4];
__device__ int   g_cnt[NNODE];
__device__ int   g_rptr[NNODE + 1];
__device__ int   g_fill[NNODE];
__device__ int   g_redges[NEDGE];
__device__ __nv_bfloat16 g_ahi[NNODE * 384];
__device__ __nv_bfloat16 g_alo[NNODE * 384];
__device__ __nv_bfloat16 g_wthi[256 * 384];
__device__ __nv_bfloat16 g_wtlo[256 * 384];

// ================= PTX helpers =================
__device__ __forceinline__ uint32_t smem_u32(const void* p) {
    uint32_t a;
    asm("{ .reg .u64 t; cvta.to.shared.u64 t, %1; cvt.u32.u64 %0, t; }" : "=r"(a) : "l"(p));
    return a;
}

#define CPA16(dst, src, sz) \
    asm volatile("cp.async.cg.shared.global [%0], [%1], 16, %2;" \
                 :: "r"(dst), "l"(src), "r"(sz))
#define CPA_COMMIT() asm volatile("cp.async.commit_group;" ::: "memory")
#define CPA_WAIT(n)  asm volatile("cp.async.wait_group %0;" :: "n"(n) : "memory")

#define LDMX4(r0, r1, r2, r3, addr) \
    asm volatile("ldmatrix.sync.aligned.m8n8.x4.shared.b16 {%0,%1,%2,%3}, [%4];" \
                 : "=r"(r0), "=r"(r1), "=r"(r2), "=r"(r3) : "r"(addr))

__device__ __forceinline__ void mma16816(float* c, const uint32_t* a, const uint32_t* b) {
    asm volatile(
        "mma.sync.aligned.m16n8k16.row.col.f32.bf16.bf16.f32 "
        "{%0,%1,%2,%3}, {%4,%5,%6,%7}, {%8,%9}, {%0,%1,%2,%3};"
        : "+f"(c[0]), "+f"(c[1]), "+f"(c[2]), "+f"(c[3])
        : "r"(a[0]), "r"(a[1]), "r"(a[2]), "r"(a[3]), "r"(b[0]), "r"(b[1]));
}

#define SWZ64(b) ((b) ^ (((b) >> 3) & 0x30))

// ---------------- utility ----------------
__global__ void zero_i(int* p, int n) {
    int i = blockIdx.x * blockDim.x + threadIdx.x;
    if (i < n) p[i] = 0;
}
__global__ void zero_f(float* p, int n) {
    int i = blockIdx.x * blockDim.x + threadIdx.x;
    if (i < n) p[i] = 0.0f;
}

// ---------------- weight prep: transpose + bf16 split ----------------
__global__ void wprep_kernel(const float* __restrict__ W, __nv_bfloat16* hi,
                             __nv_bfloat16* lo, int K, int Nn) {
    int i = blockIdx.x * blockDim.x + threadIdx.x;
    if (i >= K * Nn) return;
    int n = i / K, k = i - n * K;
    float v = W[(size_t)k * Nn + n];
    __nv_bfloat16 h = __float2bfloat16(v);
    hi[i] = h;
    lo[i] = __float2bfloat16(v - __bfloat162float(h));
}

// ---------------- activation split (layer-1 input x) ----------------
__global__ void asplit_kernel(const float* __restrict__ A, __nv_bfloat16* hi,
                              __nv_bfloat16* lo, int total) {
    int i = blockIdx.x * blockDim.x + threadIdx.x;
    if (i >= total) return;
    float v = A[i];
    __nv_bfloat16 h = __float2bfloat16(v);
    hi[i] = h;
    lo[i] = __float2bfloat16(v - __bfloat162float(h));
}

// ---------------- CSR build ----------------
__global__ void hist_kernel(const int* __restrict__ row, int* cnt, int e) {
    int i = blockIdx.x * blockDim.x + threadIdx.x;
    if (i < e) atomicAdd(&cnt[row[i]], 1);
}

__global__ void scan_kernel(const int* __restrict__ cnt, int* ptr, int* fill, int n) {
    __shared__ int sh[1024];
    __shared__ int carry;
    if (threadIdx.x == 0) carry = 0;
    __syncthreads();
    for (int base = 0; base < n; base += 1024) {
        int i = base + threadIdx.x;
        int v = (i < n) ? cnt[i] : 0;
        sh[threadIdx.x] = v;
        __syncthreads();
        for (int off = 1; off < 1024; off <<= 1) {
            int t = (threadIdx.x >= off) ? sh[threadIdx.x - off] : 0;
            __syncthreads();
            sh[threadIdx.x] += t;
            __syncthreads();
        }
        int excl = sh[threadIdx.x] - v;
        if (i < n) { ptr[i] = carry + excl; fill[i] = carry + excl; }
        __syncthreads();
        if (threadIdx.x == 1023) carry += sh[1023];
        __syncthreads();
    }
    if (threadIdx.x == 0) ptr[n] = carry;
}

__global__ void scatter_kernel(const int* __restrict__ row, int* fill, int* redges, int e) {
    int i = blockIdx.x * blockDim.x + threadIdx.x;
    if (i < e) {
        int pos = atomicAdd(&fill[row[i]], 1);
        redges[pos] = i;
    }
}

// ============ HMMA split-bf16 GEMM, 3-stage cp.async pipeline ============
// CTA tile 128(m) x 64(n), BK=32, 8 warps (4m x 2n), warp tile 32x32.
template <int NN, int KK>
__global__ __launch_bounds__(256, 2) void gemm_mma(
    const __nv_bfloat16* __restrict__ Ahi, const __nv_bfloat16* __restrict__ Alo,
    const __nv_bfloat16* __restrict__ Bhi, const __nv_bfloat16* __restrict__ Blo,
    float* __restrict__ C, int M)
{
    constexpr int BK = 32;
    constexpr int NCH = KK / BK;
    constexpr int STG = 24576;   // A hi 8K | A lo 8K | B hi 4K | B lo 4K
    extern __shared__ char smem[];
    uint32_t sb = smem_u32(smem);

    int tid = threadIdx.x;
    int lane = tid & 31, wid = tid >> 5;
    int wm = wid & 3, wn = wid >> 2;
    int m0 = blockIdx.y * 128;
    int n0 = blockIdx.x * 64;

    // ldmatrix addresses (stage-relative)
    int g = lane >> 3, lr = lane & 7;
    uint32_t aoff[2][2], boff[2][2];
#pragma unroll
    for (int mt = 0; mt < 2; mt++)
#pragma unroll
        for (int ks = 0; ks < 2; ks++) {
            int row = wm * 32 + mt * 16 + (g & 1) * 8 + lr;
            int unit = ks * 2 + (g >> 1);
            aoff[mt][ks] = SWZ64(row * 64 + unit * 16);
        }
#pragma unroll
    for (int np = 0; np < 2; np++)
#pragma unroll
        for (int ks = 0; ks < 2; ks++) {
            int row = wn * 32 + np * 16 + (g >> 1) * 8 + lr;
            int unit = ks * 2 + (g & 1);
            boff[np][ks] = 16384u + SWZ64(row * 64 + unit * 16);
        }

    // cp.async slots
    int ar0 = tid >> 2, au0 = tid & 3;
    int ar1 = (tid + 256) >> 2;
    uint32_t asw0 = SWZ64(ar0 * 64 + au0 * 16);
    uint32_t asw1 = SWZ64(ar1 * 64 + au0 * 16);
    int br = tid >> 2, bu = tid & 3;
    uint32_t bsw = SWZ64(br * 64 + bu * 16);
    long bofs = (long)(n0 + br) * KK + bu * 8;

    float acc[2][4][4];
#pragma unroll
    for (int mt = 0; mt < 2; mt++)
#pragma unroll
        for (int nt = 0; nt < 4; nt++)
#pragma unroll
            for (int j = 0; j < 4; j++) acc[mt][nt][j] = 0.f;

    auto load_stage = [&](int ch, uint32_t so) {
        int k0 = ch * BK;
        {
            int grow = m0 + ar0;
            int sz = (grow < M) ? 16 : 0;
            long go = (long)((grow < M) ? grow : 0) * KK + k0 + au0 * 8;
            CPA16(sb + so + asw0, Ahi + go, sz);
            CPA16(sb + so + 8192 + asw0, Alo + go, sz);
        }
        {
            int grow = m0 + ar1;
            int sz = (grow < M) ? 16 : 0;
            long go = (long)((grow < M) ? grow : 0) * KK + k0 + au0 * 8;
            CPA16(sb + so + asw1, Ahi + go, sz);
            CPA16(sb + so + 8192 + asw1, Alo + go, sz);
        }
        {
            long go = bofs + k0;
            CPA16(sb + so + 16384 + bsw, Bhi + go, 16);
            CPA16(sb + so + 20480 + bsw, Blo + go, 16);
        }
    };

    auto compute_stage = [&](uint32_t so) {
#pragma unroll
        for (int ks = 0; ks < 2; ks++) {
            uint32_t ah[2][4], al[2][4], bh[4][2], bl[4][2];
#pragma unroll
            for (int mt = 0; mt < 2; mt++) {
                LDMX4(ah[mt][0], ah[mt][1], ah[mt][2], ah[mt][3], sb + so + aoff[mt][ks]);
                LDMX4(al[mt][0], al[mt][1], al[mt][2], al[mt][3], sb + so + 8192 + aoff[mt][ks]);
            }
#pragma unroll
            for (int np = 0; np < 2; np++) {
                LDMX4(bh[2 * np][0], bh[2 * np][1], bh[2 * np + 1][0], bh[2 * np + 1][1],
                      sb + so + boff[np][ks]);
                LDMX4(bl[2 * np][0], bl[2 * np][1], bl[2 * np + 1][0], bl[2 * np + 1][1],
                      sb + so + 4096 + boff[np][ks]);
            }
#pragma unroll
            for (int mt = 0; mt < 2; mt++)
#pragma unroll
                for (int nt = 0; nt < 4; nt++) {
                    mma16816(acc[mt][nt], ah[mt], bh[nt]);
                    mma16816(acc[mt][nt], ah[mt], bl[nt]);
                    mma16816(acc[mt][nt], al[mt], bh[nt]);
                }
        }
    };

    // 3-stage pipeline, one __syncthreads per chunk
    load_stage(0, 0);
    CPA_COMMIT();
    load_stage(1, STG);
    CPA_COMMIT();
#pragma unroll 1
    for (int ch = 0; ch < NCH; ch++) {
        uint32_t so = (uint32_t)(ch % 3) * STG;
        if (ch + 1 < NCH) { CPA_WAIT(1); } else { CPA_WAIT(0); }
        __syncthreads();
        if (ch + 2 < NCH) {
            load_stage(ch + 2, (uint32_t)((ch + 2) % 3) * STG);
            CPA_COMMIT();
        }
        compute_stage(so);
    }

    // epilogue
#pragma unroll
    for (int mt = 0; mt < 2; mt++) {
        int m = m0 + wm * 32 + mt * 16 + (lane >> 2);
#pragma unroll
        for (int nt = 0; nt < 4; nt++) {
            int n = n0 + wn * 32 + nt * 8 + (lane & 3) * 2;
            if (m < M)
                *reinterpret_cast<float2*>(C + (size_t)m * NN + n) =
                    make_float2(acc[mt][nt][0], acc[mt][nt][1]);
            if (m + 8 < M)
                *reinterpret_cast<float2*>(C + (size_t)(m + 8) * NN + n) =
                    make_float2(acc[mt][nt][2], acc[mt][nt][3]);
        }
    }
}

// ---------------- per-node attention scores ----------------
__global__ void attn_scores_kernel(
    const float* __restrict__ h, const float* __restrict__ asrc, const float* __restrict__ adst,
    float* __restrict__ ssrc, float* __restrict__ sdst, int n, int H, int C)
{
    int wid = (blockIdx.x * blockDim.x + threadIdx.x) >> 5;
    int lane = threadIdx.x & 31;
    if (wid >= n * H) return;
    int node = wid / H, hh = wid - node * H;
    const float* hp = h + (size_t)node * H * C + hh * C;
    const float* ap = asrc + hh * C;
    const float* dp = adst + hh * C;
    float ss = 0.f, sd = 0.f;
    for (int c = lane; c < C; c += 32) {
        float v = hp[c];
        ss += v * ap[c];
        sd += v * dp[c];
    }
#pragma unroll
    for (int o = 16; o; o >>= 1) {
        ss += __shfl_xor_sync(0xffffffffu, ss, o);
        sd += __shfl_xor_sync(0xffffffffu, sd, o);
    }
    if (lane == 0) { ssrc[wid] = ss; sdst[wid] = sd; }
}

// ---------------- edge scores H=4 (vectorized) ----------------
__global__ void edge_scores4_kernel(
    const int* __restrict__ row, const int* __restrict__ col, const float* __restrict__ ew,
    const float* __restrict__ ssrc, const float* __restrict__ sdst,
    float* __restrict__ aexp, float* __restrict__ denom, int e)
{
    int i = blockIdx.x * blockDim.x + threadIdx.x;
    if (i >= e) return;
    int r = row[i], c = col[i];
    float w = ew[i];
    float4 s4 = *reinterpret_cast<const float4*>(ssrc + (size_t)r * 4);
    float4 d4 = *reinterpret_cast<const float4*>(sdst + (size_t)c * 4);
    float4 o;
    float v;
    v = s4.x + d4.x; v = (v >= 0.f) ? v : NEG_SLOPE * v; o.x = expf(v * w);
    v = s4.y + d4.y; v = (v >= 0.f) ? v : NEG_SLOPE * v; o.y = expf(v * w);
    v = s4.z + d4.z; v = (v >= 0.f) ? v : NEG_SLOPE * v; o.z = expf(v * w);
    v = s4.w + d4.w; v = (v >= 0.f) ? v : NEG_SLOPE * v; o.w = expf(v * w);
    *reinterpret_cast<float4*>(aexp + (size_t)i * 4) = o;
    atomicAdd(&denom[c * 4 + 0], o.x);
    atomicAdd(&denom[c * 4 + 1], o.y);
    atomicAdd(&denom[c * 4 + 2], o.z);
    atomicAdd(&denom[c * 4 + 3], o.w);
}

// ---------------- edge scores H=1 ----------------
__global__ void edge_scores1_kernel(
    const int* __restrict__ row, const int* __restrict__ col, const float* __restrict__ ew,
    const float* __restrict__ ssrc, const float* __restrict__ sdst,
    float* __restrict__ aexp, float* __restrict__ denom, int e)
{
    int i = blockIdx.x * blockDim.x + threadIdx.x;
    if (i >= e) return;
    int r = row[i], c = col[i];
    float v = ssrc[r] + sdst[c];
    v = (v >= 0.f) ? v : NEG_SLOPE * v;
    v = expf(v * ew[i]);
    aexp[i] = v;
    atomicAdd(&denom[c], v);
}

// ---------------- reciprocal of denominators ----------------
__global__ void rdenom_kernel(float* d, int n) {
    int i = blockIdx.x * blockDim.x + threadIdx.x;
    if (i < n) d[i] = 1.0f / (d[i] + EPS_SM);
}

// ---------------- aggregation D=256 H=4: lane owns 8 contiguous cols ----------------
__global__ __launch_bounds__(256) void aggregate256_kernel(
    const float* __restrict__ h, const float* __restrict__ aexp, const float* __restrict__ rden,
    const int* __restrict__ col, const int* __restrict__ rptr, const int* __restrict__ redges,
    const float* __restrict__ bias, float* __restrict__ out, int n)
{
    int warp = (blockIdx.x * blockDim.x + threadIdx.x) >> 5;
    int lane = threadIdx.x & 31;
    if (warp >= n) return;
    int hh = lane >> 3;   // head for this lane's 8 columns
    float4 a0 = make_float4(0.f, 0.f, 0.f, 0.f);
    float4 a1 = make_float4(0.f, 0.f, 0.f, 0.f);
    int s = rptr[warp], e1 = rptr[warp + 1];
    int i = s;
    for (; i + 1 < e1; i += 2) {
        int ea = redges[i], eb = redges[i + 1];
        int ca = col[ea], cb = col[eb];
        float wa = aexp[(size_t)ea * 4 + hh] * rden[(size_t)ca * 4 + hh];
        float wb = aexp[(size_t)eb * 4 + hh] * rden[(size_t)cb * 4 + hh];
        const float4* pa = reinterpret_cast<const float4*>(h + (size_t)ca * 256 + lane * 8);
        const float4* pb = reinterpret_cast<const float4*>(h + (size_t)cb * 256 + lane * 8);
        float4 va0 = pa[0], va1 = pa[1], vb0 = pb[0], vb1 = pb[1];
        a0.x += wa * va0.x; a0.y += wa * va0.y; a0.z += wa * va0.z; a0.w += wa * va0.w;
        a1.x += wa * va1.x; a1.y += wa * va1.y; a1.z += wa * va1.z; a1.w += wa * va1.w;
        a0.x += wb * vb0.x; a0.y += wb * vb0.y; a0.z += wb * vb0.z; a0.w += wb * vb0.w;
        a1.x += wb * vb1.x; a1.y += wb * vb1.y; a1.z += wb * vb1.z; a1.w += wb * vb1.w;
    }
    if (i < e1) {
        int e = redges[i];
        int c = col[e];
        float w = aexp[(size_t)e * 4 + hh] * rden[(size_t)c * 4 + hh];
        const float4* p = reinterpret_cast<const float4*>(h + (size_t)c * 256 + lane * 8);
        float4 v0 = p[0], v1 = p[1];
        a0.x += w * v0.x; a0.y += w * v0.y; a0.z += w * v0.z; a0.w += w * v0.w;
        a1.x += w * v1.x; a1.y += w * v1.y; a1.z += w * v1.z; a1.w += w * v1.w;
    }
    const float4* bp = reinterpret_cast<const float4*>(bias + lane * 8);
    float4 b0 = bp[0], b1 = bp[1];
    a0.x += b0.x; a0.y += b0.y; a0.z += b0.z; a0.w += b0.w;
    a1.x += b1.x; a1.y += b1.y; a1.z += b1.z; a1.w += b1.w;
    float4* op = reinterpret_cast<float4*>(out + (size_t)warp * 256 + lane * 8);
    op[0] = a0;
    op[1] = a1;
}

// ---------------- aggregation D=128 H=1: lane owns 4 contiguous cols ----------------
__global__ __launch_bounds__(256) void aggregate128_kernel(
    const float* __restrict__ h, const float* __restrict__ aexp, const float* __restrict__ rden,
    const int* __restrict__ col, const int* __restrict__ rptr, const int* __restrict__ redges,
    const float* __restrict__ bias, float* __restrict__ out, int n)
{
    int warp = (blockIdx.x * blockDim.x + threadIdx.x) >> 5;
    int lane = threadIdx.x & 31;
    if (warp >= n) return;
    float4 a0 = make_float4(0.f, 0.f, 0.f, 0.f);
    int s = rptr[warp], e1 = rptr[warp + 1];
    int i = s;
    for (; i + 1 < e1; i += 2) {
        int ea = redges[i], eb = redges[i + 1];
        int ca = col[ea], cb = col[eb];
        float wa = aexp[ea] * rden[ca];
        float wb = aexp[eb] * rden[cb];
        float4 va = *reinterpret_cast<const float4*>(h + (size_t)ca * 128 + lane * 4);
        float4 vb = *reinterpret_cast<const float4*>(h + (size_t)cb * 128 + lane * 4);
        a0.x += wa * va.x; a0.y += wa * va.y; a0.z += wa * va.z; a0.w += wa * va.w;
        a0.x += wb * vb.x; a0.y += wb * vb.y; a0.z += wb * vb.z; a0.w += wb * vb.w;
    }
    if (i < e1) {
        int e = redges[i];
        int c = col[e];
        float w = aexp[e] * rden[c];
        float4 v = *reinterpret_cast<const float4*>(h + (size_t)c * 128 + lane * 4);
        a0.x += w * v.x; a0.y += w * v.y; a0.z += w * v.z; a0.w += w * v.w;
    }
    float4 b0 = *reinterpret_cast<const float4*>(bias + lane * 4);
    a0.x += b0.x; a0.y += b0.y; a0.z += b0.z; a0.w += b0.w;
    *reinterpret_cast<float4*>(out + (size_t)warp * 128 + lane * 4) = a0;
}

// ---------------- LN+ELU -> bf16 hi/lo split ----------------
template <int DK>
__global__ __launch_bounds__(256) void ln_split_kernel(
    const float* __restrict__ in, const float* __restrict__ g, const float* __restrict__ b,
    __nv_bfloat16* __restrict__ hi, __nv_bfloat16* __restrict__ lo, int n)
{
    const int D = DK * 32;
    int warp = (blockIdx.x * blockDim.x + threadIdx.x) >> 5;
    int lane = threadIdx.x & 31;
    if (warp >= n) return;
    float v[DK];
    float sum = 0.f, sumsq = 0.f;
#pragma unroll
    for (int k = 0; k < DK; k++) {
        v[k] = in[(size_t)warp * D + k * 32 + lane];
        sum += v[k];
        sumsq += v[k] * v[k];
    }
#pragma unroll
    for (int o = 16; o; o >>= 1) {
        sum += __shfl_xor_sync(0xffffffffu, sum, o);
        sumsq += __shfl_xor_sync(0xffffffffu, sumsq, o);
    }
    float mu = sum / (float)D;
    float var = sumsq / (float)D - mu * mu;
    float r = rsqrtf(var + EPS_LN);
#pragma unroll
    for (int k = 0; k < DK; k++) {
        int d = k * 32 + lane;
        float y = (v[k] - mu) * r * g[d] + b[d];
        y = (y > 0.f) ? y : expm1f(y);
        __nv_bfloat16 hh = __float2bfloat16(y);
        hi[(size_t)warp * D + d] = hh;
        lo[(size_t)warp * D + d] = __float2bfloat16(y - __bfloat162float(hh));
    }
}

// ---------------- final layernorm (fp32 out) ----------------
template <int DK>
__global__ __launch_bounds__(256) void ln_kernel(
    const float* __restrict__ in, const float* __restrict__ g, const float* __restrict__ b,
    float* __restrict__ out, int n)
{
    const int D = DK * 32;
    int warp = (blockIdx.x * blockDim.x + threadIdx.x) >> 5;
    int lane = threadIdx.x & 31;
    if (warp >= n) return;
    float v[DK];
    float sum = 0.f, sumsq = 0.f;
#pragma unroll
    for (int k = 0; k < DK; k++) {
        v[k] = in[(size_t)warp * D + k * 32 + lane];
        sum += v[k];
        sumsq += v[k] * v[k];
    }
#pragma unroll
    for (int o = 16; o; o >>= 1) {
        sum += __shfl_xor_sync(0xffffffffu, sum, o);
        sumsq += __shfl_xor_sync(0xffffffffu, sumsq, o);
    }
    float mu = sum / (float)D;
    float var = sumsq / (float)D - mu * mu;
    float r = rsqrtf(var + EPS_LN);
#pragma unroll
    for (int k = 0; k < DK; k++) {
        int d = k * 32 + lane;
        out[(size_t)warp * D + d] = (v[k] - mu) * r * g[d] + b[d];
    }
}

// ---------------- host orchestration ----------------
static inline int ceil_div(int a, int b) { return (a + b - 1) / b; }

extern "C" void kernel_launch(void* const* d_in, const int* in_sizes, int n_in,
                              void* d_out, int out_size) {
    const float* x   = (const float*)d_in[0];
    const int*   ei  = (const int*)d_in[1];
    const float* ew  = (const float*)d_in[2];
    const float* W1  = (const float*)d_in[3];
    const float* as1 = (const float*)d_in[4];
    const float* ad1 = (const float*)d_in[5];
    const float* b1  = (const float*)d_in[6];
    const float* g1  = (const float*)d_in[7];
    const float* be1 = (const float*)d_in[8];
    const float* W2  = (const float*)d_in[9];
    const float* as2 = (const float*)d_in[10];
    const float* ad2 = (const float*)d_in[11];
    const float* b2  = (const float*)d_in[12];
    const float* g2  = (const float*)d_in[13];
    const float* be2 = (const float*)d_in[14];
    const float* W3  = (const float*)d_in[15];
    const float* as3 = (const float*)d_in[16];
    const float* ad3 = (const float*)d_in[17];
    const float* b3  = (const float*)d_in[18];
    const float* g3  = (const float*)d_in[19];
    const float* be3 = (const float*)d_in[20];
    float* out = (float*)d_out;

    const int* row = ei;
    const int* col = ei + NEDGE;

    float *h, *agg, *alpha, *denom, *ssrc, *sdst;
    int *cnt, *rptr, *fill, *redges;
    __nv_bfloat16 *ahi, *alo, *wthi, *wtlo;
    cudaGetSymbolAddress((void**)&h, g_h);
    cudaGetSymbolAddress((void**)&agg, g_agg);
    cudaGetSymbolAddress((void**)&alpha, g_alpha);
    cudaGetSymbolAddress((void**)&denom, g_denom);
    cudaGetSymbolAddress((void**)&ssrc, g_ssrc);
    cudaGetSymbolAddress((void**)&sdst, g_sdst);
    cudaGetSymbolAddress((void**)&cnt, g_cnt);
    cudaGetSymbolAddress((void**)&rptr, g_rptr);
    cudaGetSymbolAddress((void**)&fill, g_fill);
    cudaGetSymbolAddress((void**)&redges, g_redges);
    cudaGetSymbolAddress((void**)&ahi, g_ahi);
    cudaGetSymbolAddress((void**)&alo, g_alo);
    cudaGetSymbolAddress((void**)&wthi, g_wthi);
    cudaGetSymbolAddress((void**)&wtlo, g_wtlo);

    const int TB = 256;
    const int eb = ceil_div(NEDGE, TB);
    const int mtiles = ceil_div(NNODE, 128);
    const int SMEM = 3 * 24576;   // 73728

    cudaFuncSetAttribute(gemm_mma<256, 384>, cudaFuncAttributeMaxDynamicSharedMemorySize, SMEM);
    cudaFuncSetAttribute(gemm_mma<256, 256>, cudaFuncAttributeMaxDynamicSharedMemorySize, SMEM);
    cudaFuncSetAttribute(gemm_mma<128, 256>, cudaFuncAttributeMaxDynamicSharedMemorySize, SMEM);

    // Launch order arranged so launch index 5 (ncu -s 5 -c 1) = layer-1 GEMM.
    asplit_kernel<<<ceil_div(NNODE * 384, TB), TB>>>(x, ahi, alo, NNODE * 384);      // 0
    wprep_kernel<<<ceil_div(384 * 256, TB), TB>>>(W1, wthi, wtlo, 384, 256);         // 1
    zero_i<<<ceil_div(NNODE, TB), TB>>>(cnt, NNODE);                                 // 2
    hist_kernel<<<eb, TB>>>(row, cnt, NEDGE);                                        // 3
    scan_kernel<<<1, 1024>>>(cnt, rptr, fill, NNODE);                                // 4
    gemm_mma<256, 384><<<dim3(4, mtiles), 256, SMEM>>>(ahi, alo, wthi, wtlo, h, NNODE); // 5 <- profiled
    scatter_kernel<<<eb, TB>>>(row, fill, redges, NEDGE);                            // 6

    // =============== Layer 1 (rest) ===============
    attn_scores_kernel<<<ceil_div(NNODE * 4 * 32, TB), TB>>>(h, as1, ad1, ssrc, sdst, NNODE, 4, 64);
    zero_f<<<ceil_div(NNODE * 4, TB), TB>>>(denom, NNODE * 4);
    edge_scores4_kernel<<<eb, TB>>>(row, col, ew, ssrc, sdst, alpha, denom, NEDGE);
    rdenom_kernel<<<ceil_div(NNODE * 4, TB), TB>>>(denom, NNODE * 4);
    aggregate256_kernel<<<ceil_div(NNODE * 32, TB), TB>>>(h, alpha, denom, col, rptr, redges, b1, agg, NNODE);
    ln_split_kernel<8><<<ceil_div(NNODE * 32, TB), TB>>>(agg, g1, be1, ahi, alo, NNODE);

    // =============== Layer 2 ===============
    wprep_kernel<<<ceil_div(256 * 256, TB), TB>>>(W2, wthi, wtlo, 256, 256);
    gemm_mma<256, 256><<<dim3(4, mtiles), 256, SMEM>>>(ahi, alo, wthi, wtlo, h, NNODE);
    attn_scores_kernel<<<ceil_div(NNODE * 4 * 32, TB), TB>>>(h, as2, ad2, ssrc, sdst, NNODE, 4, 64);
    zero_f<<<ceil_div(NNODE * 4, TB), TB>>>(denom, NNODE * 4);
    edge_scores4_kernel<<<eb, TB>>>(row, col, ew, ssrc, sdst, alpha, denom, NEDGE);
    rdenom_kernel<<<ceil_div(NNODE * 4, TB), TB>>>(denom, NNODE * 4);
    aggregate256_kernel<<<ceil_div(NNODE * 32, TB), TB>>>(h, alpha, denom, col, rptr, redges, b2, agg, NNODE);
    ln_split_kernel<8><<<ceil_div(NNODE * 32, TB), TB>>>(agg, g2, be2, ahi, alo, NNODE);

    // =============== Layer 3 ===============
    wprep_kernel<<<ceil_div(256 * 128, TB), TB>>>(W3, wthi, wtlo, 256, 128);
    gemm_mma<128, 256><<<dim3(2, mtiles), 256, SMEM>>>(ahi, alo, wthi, wtlo, h, NNODE);
    attn_scores_kernel<<<ceil_div(NNODE * 32, TB), TB>>>(h, as3, ad3, ssrc, sdst, NNODE, 1, 128);
    zero_f<<<ceil_div(NNODE, TB), TB>>>(denom, NNODE);
    edge_scores1_kernel<<<eb, TB>>>(row, col, ew, ssrc, sdst, alpha, denom, NEDGE);
    rdenom_kernel<<<ceil_div(NNODE, TB), TB>>>(denom, NNODE);
    aggregate128_kernel<<<ceil_div(NNODE * 32, TB), TB>>>(h, alpha, denom, col, rptr, redges, b3, agg, NNODE);
    ln_kernel<4><<<ceil_div(NNODE * 32, TB), TB>>>(agg, g3, be3, out, NNODE);
}